// round 16
// baseline (speedup 1.0000x reference)
#include <cuda_runtime.h>
#include <math.h>
#include <stdint.h>

// ---------------- problem constants ----------------
constexpr int CB   = 2;
constexpr int CS   = 1024;
constexpr int CH   = 1024;
constexpr int CNH  = 16;
constexpr int CNKV = 4;
constexpr int CDH  = 64;
constexpr int CI   = 4096;
constexpr int CE   = 8;
constexpr int CT   = CB * CS;          // 2048 tokens
constexpr int CSLOTS = 2 * CT;
constexpr float CEPS = 1e-5f;

// ---------------- device scratch ----------------
__device__ float g_q[CT * CNH * CDH];
__device__ float g_k[CT * CNKV * CDH];
__device__ float g_v[CT * CNKV * CDH];
__device__ float g_aproj[CT * CH];
__device__ float g_x[CT * CH];
__device__ float g_h2[CT * CH];
__device__ float g_mid1[(long)CSLOTS * CI];
__device__ float g_mid2[(long)CSLOTS * CI];
__device__ float g_moe[CT * CH];
__device__ int   g_topi[CT * 2];
__device__ float g_topw[CT * 2];
__device__ int   g_tok[CE * CT];
__device__ float g_etw[CE * CT];
__device__ int   g_cnt[CE];
__device__ int   g_off[CE + 1];
// packed bf16x2 (even_k lo16, odd_k hi16) hi/lo split activations
__device__ uint32_t g_hnh[CT * 512], g_hnl[CT * 512];
__device__ uint32_t g_ath[CT * 512], g_atl[CT * 512];
__device__ uint32_t g_h2h[CT * 512], g_h2l[CT * 512];
__device__ uint32_t g_m1h[(long)CSLOTS * 2048], g_m1l[(long)CSLOTS * 2048];
// packed split weights
__device__ uint32_t g_qwh[512 * 1024], g_qwl[512 * 1024];
__device__ uint32_t g_kwh[512 * 256],  g_kwl[512 * 256];
__device__ uint32_t g_vwh[512 * 256],  g_vwl[512 * 256];
__device__ uint32_t g_owh[512 * 1024], g_owl[512 * 1024];
__device__ uint32_t g_wih[(long)8 * 512 * 4096],  g_wil[(long)8 * 512 * 4096];
__device__ uint32_t g_wvh[(long)8 * 512 * 4096],  g_wvl[(long)8 * 512 * 4096];
__device__ uint32_t g_woh[(long)8 * 2048 * 1024], g_wol[(long)8 * 2048 * 1024];

// ---------------- bf16 split helpers (verified) ----------------
__device__ __forceinline__ uint32_t bf16_rne_bits(float x) {
    uint32_t u = __float_as_uint(x);
    uint32_t r = u + 0x7FFFu + ((u >> 16) & 1u);
    return r & 0xFFFF0000u;
}
__device__ __forceinline__ void split_pack(float x0, float x1, uint32_t& hi, uint32_t& lo) {
    uint32_t h0b = bf16_rne_bits(x0);
    uint32_t h1b = bf16_rne_bits(x1);
    float l0 = x0 - __uint_as_float(h0b);
    float l1 = x1 - __uint_as_float(h1b);
    uint32_t l0b = bf16_rne_bits(l0);
    uint32_t l1b = bf16_rne_bits(l1);
    hi = (h0b >> 16) | (h1b & 0xFFFF0000u);
    lo = (l0b >> 16) | (l1b & 0xFFFF0000u);
}

__device__ __forceinline__ void mma_bf16(float* c, const uint32_t* a, const uint32_t* b) {
    asm volatile(
        "mma.sync.aligned.m16n8k16.row.col.f32.bf16.bf16.f32 "
        "{%0,%1,%2,%3}, {%4,%5,%6,%7}, {%8,%9}, {%0,%1,%2,%3};"
        : "+f"(c[0]), "+f"(c[1]), "+f"(c[2]), "+f"(c[3])
        : "r"(a[0]), "r"(a[1]), "r"(a[2]), "r"(a[3]), "r"(b[0]), "r"(b[1]));
}

// ---------------- cp.async helpers ----------------
__device__ __forceinline__ uint32_t smem_u32(const void* p) {
    uint32_t a;
    asm("{ .reg .u64 t; cvta.to.shared.u64 t, %1; cvt.u32.u64 %0, t; }" : "=r"(a) : "l"(p));
    return a;
}
__device__ __forceinline__ void cp16(uint32_t dst, const void* src, int sz) {
    asm volatile("cp.async.cg.shared.global [%0], [%1], 16, %2;"
                 :: "r"(dst), "l"(src), "r"(sz) : "memory");
}
#define CP_COMMIT() asm volatile("cp.async.commit_group;" ::: "memory")
#define CP_WAIT0()  asm volatile("cp.async.wait_group 0;" ::: "memory")

// ================= bf16x3 mma GEMM core, BK=32, dynamic smem =================
// 128x128 block tile, 256 threads (8 warps), warp tile 32x64, K-tile 32
// (2 k-steps of 16 per buffer), double-buffered cp.async fills.
// Dyn smem layout (uint32): Ahi[2][128][20] | Alo[2][128][20] | Bhi[2][16][136] | Blo[2][16][136]
constexpr int GA_STRIDE = 20;                      // k-pairs padded 16->20
constexpr int GA_BUF = 128 * GA_STRIDE;            // 2560
constexpr int GB_STRIDE = 136;
constexpr int GB_BUF = 16 * GB_STRIDE;             // 2176
constexpr int GEMM_SMEM = (2 * GA_BUF * 2 + 2 * GB_BUF * 2) * 4;   // 75776 B

template <bool GATHER, bool SCATTER>
__device__ __forceinline__ void gemm_core(
    const uint32_t* __restrict__ Ah, const uint32_t* __restrict__ Al, int lda2,
    const uint32_t* __restrict__ Bh, const uint32_t* __restrict__ Bl, int ldb,
    float* __restrict__ C, int ldc,
    int M, int K,
    int row_base, int col_base,
    const int* __restrict__ row_idx, const float* __restrict__ row_w)
{
    extern __shared__ uint32_t dsm[];
    uint32_t* sAh = dsm;
    uint32_t* sAl = dsm + 2 * GA_BUF;
    uint32_t* sBh = dsm + 4 * GA_BUF;
    uint32_t* sBl = dsm + 4 * GA_BUF + 2 * GB_BUF;

    int tid  = threadIdx.x;
    int lane = tid & 31;
    int warp = tid >> 5;
    int g  = lane >> 2;
    int t4 = lane & 3;
    int m_warp = (warp & 3) * 32;
    int n_warp = (warp >> 2) * 64;

    // A loader: row m_l = tid>>1, k-pair half kq = (tid&1)*8 (8 uint32 = 2 chunks)
    int m_l = tid >> 1;
    int kq  = (tid & 1) * 8;
    int ar  = row_base + m_l;
    bool aval = ar < M;
    const uint32_t* ah_src = Ah;
    const uint32_t* al_src = Al;
    if (aval) {
        int r = GATHER ? row_idx[ar] : ar;
        long ro = (long)r * lda2 + kq;
        ah_src = Ah + ro; al_src = Al + ro;
    }
    int azf = aval ? 16 : 0;
    uint32_t adst0 = smem_u32(&sAh[m_l * GA_STRIDE + kq]);
    uint32_t adst1 = smem_u32(&sAl[m_l * GA_STRIDE + kq]);
    // B loader: k-pair row kr = tid>>4 (0..15), n chunk nq = (tid&15)*8
    int kr = tid >> 4;
    int nq = (tid & 15) * 8;
    const uint32_t* bh_src = Bh + (long)kr * ldb + col_base + nq;
    const uint32_t* bl_src = Bl + (long)kr * ldb + col_base + nq;
    uint32_t bdst0 = smem_u32(&sBh[kr * GB_STRIDE + nq]);
    uint32_t bdst1 = smem_u32(&sBl[kr * GB_STRIDE + nq]);

    float acc[2][8][4];
#pragma unroll
    for (int i = 0; i < 2; i++)
#pragma unroll
        for (int j = 0; j < 8; j++)
#pragma unroll
            for (int l = 0; l < 4; l++) acc[i][j][l] = 0.f;

    // issue tile 0
    {
        cp16(adst0,      ah_src,     azf);
        cp16(adst0 + 16, ah_src + 4, azf);
        cp16(adst1,      al_src,     azf);
        cp16(adst1 + 16, al_src + 4, azf);
        cp16(bdst0,      bh_src,     16);
        cp16(bdst0 + 16, bh_src + 4, 16);
        cp16(bdst1,      bl_src,     16);
        cp16(bdst1 + 16, bl_src + 4, 16);
        CP_COMMIT();
    }

    int KT = K >> 5;                      // K / 32
    for (int kt = 0; kt < KT; kt++) {
        CP_WAIT0();
        __syncthreads();
        if (kt + 1 < KT) {
            int nb = (kt + 1) & 1;
            long ao = (long)(kt + 1) * 16;
            long bo = (long)(kt + 1) * 16 * ldb;
            uint32_t aoff = (uint32_t)(nb * GA_BUF * 4);
            uint32_t boff = (uint32_t)(nb * GB_BUF * 4);
            cp16(adst0 + aoff,      ah_src + ao,     azf);
            cp16(adst0 + aoff + 16, ah_src + ao + 4, azf);
            cp16(adst1 + aoff,      al_src + ao,     azf);
            cp16(adst1 + aoff + 16, al_src + ao + 4, azf);
            cp16(bdst0 + boff,      bh_src + bo,     16);
            cp16(bdst0 + boff + 16, bh_src + bo + 4, 16);
            cp16(bdst1 + boff,      bl_src + bo,     16);
            cp16(bdst1 + boff + 16, bl_src + bo + 4, 16);
            CP_COMMIT();
        }

        int buf = kt & 1;
        const uint32_t* cAh = sAh + buf * GA_BUF;
        const uint32_t* cAl = sAl + buf * GA_BUF;
        const uint32_t* cBh = sBh + buf * GB_BUF;
        const uint32_t* cBl = sBl + buf * GB_BUF;
#pragma unroll
        for (int ks = 0; ks < 2; ks++) {
            int kpb = ks * 8;
            uint32_t ah[2][4], al[2][4];
#pragma unroll
            for (int mf = 0; mf < 2; mf++) {
                int mb = m_warp + mf * 16 + g;
                ah[mf][0] = cAh[mb * GA_STRIDE + kpb + t4];
                al[mf][0] = cAl[mb * GA_STRIDE + kpb + t4];
                ah[mf][1] = cAh[(mb + 8) * GA_STRIDE + kpb + t4];
                al[mf][1] = cAl[(mb + 8) * GA_STRIDE + kpb + t4];
                ah[mf][2] = cAh[mb * GA_STRIDE + kpb + t4 + 4];
                al[mf][2] = cAl[mb * GA_STRIDE + kpb + t4 + 4];
                ah[mf][3] = cAh[(mb + 8) * GA_STRIDE + kpb + t4 + 4];
                al[mf][3] = cAl[(mb + 8) * GA_STRIDE + kpb + t4 + 4];
            }
            uint32_t bh[8][2], bl[8][2];
#pragma unroll
            for (int nf = 0; nf < 8; nf++) {
                int nb2 = n_warp + nf * 8 + g;
                bh[nf][0] = cBh[(kpb + t4) * GB_STRIDE + nb2];
                bl[nf][0] = cBl[(kpb + t4) * GB_STRIDE + nb2];
                bh[nf][1] = cBh[(kpb + t4 + 4) * GB_STRIDE + nb2];
                bl[nf][1] = cBl[(kpb + t4 + 4) * GB_STRIDE + nb2];
            }
#pragma unroll
            for (int mf = 0; mf < 2; mf++)
#pragma unroll
                for (int nf = 0; nf < 8; nf++) {
                    mma_bf16(acc[mf][nf], ah[mf], bh[nf]);
                    mma_bf16(acc[mf][nf], al[mf], bh[nf]);
                    mma_bf16(acc[mf][nf], ah[mf], bl[nf]);
                }
        }
    }

    // ---- epilogue (verified) ----
#pragma unroll
    for (int mf = 0; mf < 2; mf++) {
        int r0 = row_base + m_warp + mf * 16 + g;
        int r1 = r0 + 8;
        bool v0 = r0 < M, v1 = r1 < M;
        if (!SCATTER) {
#pragma unroll
            for (int nf = 0; nf < 8; nf++) {
                int c = col_base + n_warp + nf * 8 + t4 * 2;
                if (v0) *(float2*)&C[(long)r0 * ldc + c] = make_float2(acc[mf][nf][0], acc[mf][nf][1]);
                if (v1) *(float2*)&C[(long)r1 * ldc + c] = make_float2(acc[mf][nf][2], acc[mf][nf][3]);
            }
        } else {
            int tk0 = 0, tk1 = 0; float w0 = 0.f, w1 = 0.f;
            if (v0) { tk0 = row_idx[r0]; w0 = row_w[r0]; }
            if (v1) { tk1 = row_idx[r1]; w1 = row_w[r1]; }
#pragma unroll
            for (int nf = 0; nf < 8; nf++) {
                int c = col_base + n_warp + nf * 8 + t4 * 2;
                if (v0) {
                    atomicAdd(&C[(long)tk0 * ldc + c],     w0 * acc[mf][nf][0]);
                    atomicAdd(&C[(long)tk0 * ldc + c + 1], w0 * acc[mf][nf][1]);
                }
                if (v1) {
                    atomicAdd(&C[(long)tk1 * ldc + c],     w1 * acc[mf][nf][2]);
                    atomicAdd(&C[(long)tk1 * ldc + c + 1], w1 * acc[mf][nf][3]);
                }
            }
        }
    }
}

// ---------------- weight convert: grid-stride, 8 floats/thread/iter ----------------
__global__ __launch_bounds__(256) void wconv_kernel(
    const float* __restrict__ in, uint32_t* __restrict__ oh, uint32_t* __restrict__ ol,
    long kp_total, int N)
{
    long work = kp_total * (long)(N >> 3);
    long stride = (long)gridDim.x * 256;
    for (long idx = (long)blockIdx.x * 256 + threadIdx.x; idx < work; idx += stride) {
        long kp = idx / (N >> 3);
        int  nq = (int)(idx % (N >> 3));
        const float* p0 = in + (2 * kp) * (long)N + 8 * nq;
        float4 a0 = *(const float4*)p0;
        float4 a1 = *(const float4*)(p0 + 4);
        float4 b0 = *(const float4*)(p0 + N);
        float4 b1 = *(const float4*)(p0 + N + 4);
        uint4 h0, l0, h1, l1;
        split_pack(a0.x, b0.x, h0.x, l0.x);
        split_pack(a0.y, b0.y, h0.y, l0.y);
        split_pack(a0.z, b0.z, h0.z, l0.z);
        split_pack(a0.w, b0.w, h0.w, l0.w);
        split_pack(a1.x, b1.x, h1.x, l1.x);
        split_pack(a1.y, b1.y, h1.y, l1.y);
        split_pack(a1.z, b1.z, h1.z, l1.z);
        split_pack(a1.w, b1.w, h1.w, l1.w);
        long o = kp * (long)N + 8 * nq;
        *(uint4*)&oh[o]     = h0;
        *(uint4*)&oh[o + 4] = h1;
        *(uint4*)&ol[o]     = l0;
        *(uint4*)&ol[o + 4] = l1;
    }
}

// ---------------- rmsnorm: optional residual / fp32 out / packed out ----------------
__global__ __launch_bounds__(256) void rmsnorm_kernel(
    const float* __restrict__ in, const float* __restrict__ sc,
    const float* __restrict__ resid, float* __restrict__ out,
    uint32_t* __restrict__ outh, uint32_t* __restrict__ outl)
{
    long row = blockIdx.x;
    int tid = threadIdx.x;
    float4 v = *(const float4*)(in + row * CH + tid * 4);
    float ss = v.x * v.x + v.y * v.y + v.z * v.z + v.w * v.w;
    __shared__ float red[256];
    red[tid] = ss;
    __syncthreads();
    for (int s = 128; s > 0; s >>= 1) {
        if (tid < s) red[tid] += red[tid + s];
        __syncthreads();
    }
    float r = rsqrtf(red[0] * (1.0f / CH) + CEPS);
    float4 s4 = *(const float4*)(sc + tid * 4);
    float o0 = v.x * r * s4.x, o1 = v.y * r * s4.y, o2 = v.z * r * s4.z, o3 = v.w * r * s4.w;
    if (resid) {
        float4 rr = *(const float4*)(resid + row * CH + tid * 4);
        o0 += rr.x; o1 += rr.y; o2 += rr.z; o3 += rr.w;
    }
    if (out) *(float4*)(out + row * CH + tid * 4) = make_float4(o0, o1, o2, o3);
    if (outh) {
        uint32_t h0, l0, h1, l1;
        split_pack(o0, o1, h0, l0);
        split_pack(o2, o3, h1, l1);
        *(uint2*)&outh[row * 512 + tid * 2] = make_uint2(h0, h1);
        *(uint2*)&outl[row * 512 + tid * 2] = make_uint2(l0, l1);
    }
}

// ---------------- GEMM wrappers ----------------
__global__ __launch_bounds__(256) void qkv_kernel(
    const uint32_t* __restrict__ hnh, const uint32_t* __restrict__ hnl,
    const uint32_t* __restrict__ qwh, const uint32_t* __restrict__ qwl,
    const uint32_t* __restrict__ kwh, const uint32_t* __restrict__ kwl,
    const uint32_t* __restrict__ vwh, const uint32_t* __restrict__ vwl,
    float* __restrict__ q, float* __restrict__ k, float* __restrict__ v)
{
    int x = blockIdx.x;
    const uint32_t *Bh, *Bl; float* C; int ld; int col;
    if (x < 8)       { Bh = qwh; Bl = qwl; C = q; ld = 1024; col = x * 128; }
    else if (x < 10) { Bh = kwh; Bl = kwl; C = k; ld = 256;  col = (x - 8) * 128; }
    else             { Bh = vwh; Bl = vwl; C = v; ld = 256;  col = (x - 10) * 128; }
    gemm_core<false, false>(hnh, hnl, 512, Bh, Bl, ld, C, ld, CT, CH,
                            blockIdx.y * 128, col, nullptr, nullptr);
}

__global__ __launch_bounds__(256) void oproj_kernel(
    const uint32_t* __restrict__ ath, const uint32_t* __restrict__ atl,
    const uint32_t* __restrict__ owh, const uint32_t* __restrict__ owl,
    float* __restrict__ aproj)
{
    gemm_core<false, false>(ath, atl, 512, owh, owl, CH, aproj, CH, CT, CH,
                            blockIdx.y * 128, blockIdx.x * 128, nullptr, nullptr);
}

__global__ __launch_bounds__(256) void moe_stage1_kernel(
    const uint32_t* __restrict__ h2h, const uint32_t* __restrict__ h2l,
    const uint32_t* __restrict__ wih, const uint32_t* __restrict__ wil,
    const uint32_t* __restrict__ wvh, const uint32_t* __restrict__ wvl,
    float* __restrict__ mid1, float* __restrict__ mid2,
    const int* __restrict__ tok, const int* __restrict__ cnt, const int* __restrict__ off)
{
    int z = blockIdx.z;
    int e = z >> 1;
    int which = z & 1;
    int M = cnt[e];
    int row_base = blockIdx.y * 128;
    if (row_base >= M) return;
    const uint32_t* Bh = (which ? wvh : wih) + (long)e * 512 * CI;
    const uint32_t* Bl = (which ? wvl : wil) + (long)e * 512 * CI;
    float* C = (which ? mid2 : mid1) + (long)off[e] * CI;
    gemm_core<true, false>(h2h, h2l, 512, Bh, Bl, CI, C, CI, M, CH,
                           row_base, blockIdx.x * 128, tok + e * CT, nullptr);
}

__global__ __launch_bounds__(256) void moe_stage2_kernel(
    const uint32_t* __restrict__ m1h, const uint32_t* __restrict__ m1l,
    const uint32_t* __restrict__ woh, const uint32_t* __restrict__ wol,
    float* __restrict__ moe,
    const int* __restrict__ tok, const float* __restrict__ etw,
    const int* __restrict__ cnt, const int* __restrict__ off)
{
    int e = blockIdx.z;
    int M = cnt[e];
    int row_base = blockIdx.y * 128;
    if (row_base >= M) return;
    const uint32_t* Ah = m1h + (long)off[e] * 2048;
    const uint32_t* Al = m1l + (long)off[e] * 2048;
    const uint32_t* Bh = woh + (long)e * 2048 * CH;
    const uint32_t* Bl = wol + (long)e * 2048 * CH;
    gemm_core<false, true>(Ah, Al, 2048, Bh, Bl, CH, moe, CH, M, CI,
                           row_base, blockIdx.x * 128, tok + e * CT, etw + e * CT);
}

// ---------------- RoPE ----------------
__global__ __launch_bounds__(256) void rope_kernel(
    float* __restrict__ q, float* __restrict__ k, const int* __restrict__ pos)
{
    long idx = (long)blockIdx.x * 256 + threadIdx.x;
    if (idx >= (long)CT * 20 * 32) return;
    int d = idx & 31;
    int hh = (int)((idx >> 5) % 20);
    int t = (int)(idx / (32 * 20));
    float p = (float)pos[t];
    float inv = powf(10000.0f, -((float)d) / 32.0f);
    float ang = p * inv;
    float c = cosf(ang), s = sinf(ang);
    float* ptr;
    if (hh < CNH) ptr = q + (long)t * (CNH * CDH) + hh * CDH;
    else          ptr = k + (long)t * (CNKV * CDH) + (hh - CNH) * CDH;
    float x1 = ptr[d], x2 = ptr[d + 32];
    ptr[d]      = x1 * c - x2 * s;
    ptr[d + 32] = x2 * c + x1 * s;
}

// ================= fused flash attention (verified; packed output) =================
constexpr int FA_STRIDE = 68;
constexpr int FA_REGION = 64 * FA_STRIDE;
constexpr int FA_SMEM_BYTES = 3 * FA_REGION * 4;

__global__ __launch_bounds__(256) void flash_attn_kernel(
    const float* __restrict__ q, const float* __restrict__ k, const float* __restrict__ v,
    const int* __restrict__ amask,
    uint32_t* __restrict__ attnh, uint32_t* __restrict__ attnl)
{
    extern __shared__ float sm[];
    float* Qs = sm;
    float* KP = sm + FA_REGION;
    float* Vs = sm + 2 * FA_REGION;

    int it = (int)gridDim.x - 1 - (int)blockIdx.x;
    int bh = blockIdx.y;
    int b = bh >> 4, h = bh & 15, kv = h >> 2;
    int tid = threadIdx.x;
    int ti = (tid >> 4) << 2;
    int tj = (tid & 15) << 2;

#pragma unroll
    for (int l = 0; l < 4; l++) {
        int e = tid + l * 256;
        int r = e >> 4;
        int c = (e & 15) << 2;
        float4 a = *(const float4*)(q + (long)(b * CS + it * 64 + r) * (CNH * CDH) + h * CDH + c);
        Qs[(c + 0) * FA_STRIDE + r] = a.x; Qs[(c + 1) * FA_STRIDE + r] = a.y;
        Qs[(c + 2) * FA_STRIDE + r] = a.z; Qs[(c + 3) * FA_STRIDE + r] = a.w;
    }

    float m_i[4], l_i[4], acc[4][4];
#pragma unroll
    for (int i = 0; i < 4; i++) {
        m_i[i] = -1e30f; l_i[i] = 0.f;
#pragma unroll
        for (int j = 0; j < 4; j++) acc[i][j] = 0.f;
    }

    for (int jt = 0; jt <= it; jt++) {
        __syncthreads();
#pragma unroll
        for (int l = 0; l < 4; l++) {
            int e = tid + l * 256;
            int r = e >> 4;
            int c = (e & 15) << 2;
            const float* kvbase = k + (long)(b * CS + jt * 64 + r) * (CNKV * CDH) + kv * CDH + c;
            float4 kk = *(const float4*)(kvbase);
            KP[(c + 0) * FA_STRIDE + r] = kk.x; KP[(c + 1) * FA_STRIDE + r] = kk.y;
            KP[(c + 2) * FA_STRIDE + r] = kk.z; KP[(c + 3) * FA_STRIDE + r] = kk.w;
            float4 vv = *(const float4*)(v + (long)(b * CS + jt * 64 + r) * (CNKV * CDH) + kv * CDH + c);
            *(float4*)&Vs[r * FA_STRIDE + c] = vv;
        }
        __syncthreads();

        float s[4][4] = {};
#pragma unroll 8
        for (int d = 0; d < 64; d++) {
            float4 a = *(const float4*)&Qs[d * FA_STRIDE + ti];
            float4 bb = *(const float4*)&KP[d * FA_STRIDE + tj];
            float af[4] = {a.x, a.y, a.z, a.w};
            float bf[4] = {bb.x, bb.y, bb.z, bb.w};
#pragma unroll
            for (int i = 0; i < 4; i++)
#pragma unroll
                for (int j = 0; j < 4; j++) s[i][j] += af[i] * bf[j];
        }

        int ig0 = it * 64 + ti;
        int jg0 = jt * 64 + tj;
        int msk[4];
#pragma unroll
        for (int j = 0; j < 4; j++) msk[j] = amask[b * CS + jg0 + j];
#pragma unroll
        for (int i = 0; i < 4; i++)
#pragma unroll
            for (int j = 0; j < 4; j++) {
                bool valid = (jg0 + j <= ig0 + i) && (msk[j] > 0);
                s[i][j] = valid ? s[i][j] * 0.125f : -1e9f;
            }

        float p[4][4];
#pragma unroll
        for (int i = 0; i < 4; i++) {
            float mx = fmaxf(fmaxf(s[i][0], s[i][1]), fmaxf(s[i][2], s[i][3]));
#pragma unroll
            for (int d = 1; d < 16; d <<= 1)
                mx = fmaxf(mx, __shfl_xor_sync(0xFFFFFFFFu, mx, d));
            float nm = fmaxf(m_i[i], mx);
            float alpha = expf(m_i[i] - nm);
            float rs = 0.f;
#pragma unroll
            for (int j = 0; j < 4; j++) { p[i][j] = expf(s[i][j] - nm); rs += p[i][j]; }
#pragma unroll
            for (int d = 1; d < 16; d <<= 1)
                rs += __shfl_xor_sync(0xFFFFFFFFu, rs, d);
            l_i[i] = l_i[i] * alpha + rs;
            m_i[i] = nm;
#pragma unroll
            for (int j = 0; j < 4; j++) acc[i][j] *= alpha;
        }

        __syncthreads();
#pragma unroll
        for (int i = 0; i < 4; i++)
            *(float4*)&KP[(ti + i) * FA_STRIDE + tj] =
                make_float4(p[i][0], p[i][1], p[i][2], p[i][3]);
        __syncthreads();

#pragma unroll 4
        for (int jc = 0; jc < 64; jc += 4) {
            float4 pr[4], vr[4];
#pragma unroll
            for (int i = 0; i < 4; i++) pr[i] = *(const float4*)&KP[(ti + i) * FA_STRIDE + jc];
#pragma unroll
            for (int j = 0; j < 4; j++) vr[j] = *(const float4*)&Vs[(jc + j) * FA_STRIDE + tj];
#pragma unroll
            for (int i = 0; i < 4; i++) {
                float pf[4] = {pr[i].x, pr[i].y, pr[i].z, pr[i].w};
#pragma unroll
                for (int j = 0; j < 4; j++) {
                    acc[i][0] += pf[j] * vr[j].x;
                    acc[i][1] += pf[j] * vr[j].y;
                    acc[i][2] += pf[j] * vr[j].z;
                    acc[i][3] += pf[j] * vr[j].w;
                }
            }
        }
    }

#pragma unroll
    for (int i = 0; i < 4; i++) {
        float inv = 1.0f / l_i[i];
        float o0 = acc[i][0] * inv, o1 = acc[i][1] * inv;
        float o2 = acc[i][2] * inv, o3 = acc[i][3] * inv;
        uint32_t h0, l0, h1, l1;
        split_pack(o0, o1, h0, l0);
        split_pack(o2, o3, h1, l1);
        long rb = (long)(b * CS + it * 64 + ti + i) * 512 + ((h * CDH + tj) >> 1);
        *(uint2*)&attnh[rb] = make_uint2(h0, h1);
        *(uint2*)&attnl[rb] = make_uint2(l0, l1);
    }
}

// ---------------- MoE gating ----------------
__global__ __launch_bounds__(128) void gate_kernel(
    const float* __restrict__ h2, const float* __restrict__ gw,
    int* __restrict__ topi, float* __restrict__ topw)
{
    int t = blockIdx.x;
    int tid = threadIdx.x;
    float p[8] = {};
    for (int hh = tid; hh < CH; hh += 128) {
        float x = h2[(long)t * CH + hh];
        const float* g = gw + hh * CE;
#pragma unroll
        for (int e = 0; e < 8; e++) p[e] += x * g[e];
    }
    __shared__ float red[128 * 8];
#pragma unroll
    for (int e = 0; e < 8; e++) red[tid * 8 + e] = p[e];
    __syncthreads();
    for (int s = 64; s > 0; s >>= 1) {
        if (tid < s)
#pragma unroll
            for (int e = 0; e < 8; e++) red[tid * 8 + e] += red[(tid + s) * 8 + e];
        __syncthreads();
    }
    if (tid == 0) {
        float lg[8], pr[8];
        float m = -1e30f;
#pragma unroll
        for (int e = 0; e < 8; e++) { lg[e] = red[e]; m = fmaxf(m, lg[e]); }
        float sum = 0.f;
#pragma unroll
        for (int e = 0; e < 8; e++) { pr[e] = expf(lg[e] - m); sum += pr[e]; }
        float inv = 1.0f / sum;
#pragma unroll
        for (int e = 0; e < 8; e++) pr[e] *= inv;
        int i0 = 0;
#pragma unroll
        for (int e = 1; e < 8; e++) if (pr[e] > pr[i0]) i0 = e;
        int i1 = -1;
#pragma unroll
        for (int e = 0; e < 8; e++) {
            if (e == i0) continue;
            if (i1 < 0 || pr[e] > pr[i1]) i1 = e;
        }
        topi[t * 2] = i0; topi[t * 2 + 1] = i1;
        topw[t * 2] = pr[i0]; topw[t * 2 + 1] = pr[i1];
    }
}

// ---------------- routing ----------------
__global__ __launch_bounds__(256) void route_kernel(
    const int* __restrict__ topi, const float* __restrict__ topw,
    int* __restrict__ tok, float* __restrict__ etw,
    int* __restrict__ cnt, int* __restrict__ off)
{
    int e = threadIdx.x >> 5;
    int lane = threadIdx.x & 31;
    int count = 0;
    for (int base = 0; base < CT; base += 32) {
        int t = base + lane;
        int i0 = topi[t * 2], i1 = topi[t * 2 + 1];
        bool sel = (i0 == e) || (i1 == e);
        float w = (i0 == e) ? topw[t * 2] : topw[t * 2 + 1];
        unsigned m = __ballot_sync(0xFFFFFFFFu, sel);
        int pos = count + __popc(m & ((1u << lane) - 1u));
        if (sel) {
            tok[e * CT + pos] = t;
            etw[e * CT + pos] = w;
        }
        count += __popc(m);
    }
    if (lane == 0) cnt[e] = count;
    __syncthreads();
    if (threadIdx.x == 0) {
        int s = 0;
        for (int i = 0; i < CE; i++) { off[i] = s; s += cnt[i]; }
        off[CE] = s;
    }
}

// ---------------- GEGLU -> packed split ----------------
__global__ __launch_bounds__(256) void glu_kernel(
    const float* __restrict__ m1, const float* __restrict__ m2,
    uint32_t* __restrict__ oh, uint32_t* __restrict__ ol,
    const int* __restrict__ off)
{
    int row = blockIdx.y;
    if (row >= off[CE]) return;
    int p = blockIdx.x * 256 + threadIdx.x;
    long base = (long)row * CI + 2 * p;
    float2 a = *(const float2*)&m1[base];
    float2 b = *(const float2*)&m2[base];
    float g0 = 0.5f * a.x * (1.0f + tanhf(0.7978845608028654f * (a.x + 0.044715f * a.x * a.x * a.x))) * b.x;
    float g1 = 0.5f * a.y * (1.0f + tanhf(0.7978845608028654f * (a.y + 0.044715f * a.y * a.y * a.y))) * b.y;
    uint32_t h, l;
    split_pack(g0, g1, h, l);
    oh[(long)row * 2048 + p] = h;
    ol[(long)row * 2048 + p] = l;
}

// ---------------- zero fill ----------------
__global__ __launch_bounds__(256) void zero_kernel(float* __restrict__ p)
{
    p[(long)blockIdx.x * 256 + threadIdx.x] = 0.f;
}

// ---------------- host orchestration ----------------
#define SYMADDR(var, ptr) do { void* _p = nullptr; cudaGetSymbolAddress(&_p, var); ptr = (decltype(ptr))_p; } while (0)

static inline int wblocks(long kp_total, int N) {
    long work = kp_total * (long)(N >> 3);
    long b = (work + 255) / 256;
    return (int)(b < 2048 ? b : 2048);
}

extern "C" void kernel_launch(void* const* d_in, const int* in_sizes, int n_in,
                              void* d_out, int out_size)
{
    const float* hidden   = (const float*)d_in[0];
    const int*   amask    = (const int*)d_in[1];
    const int*   posids   = (const int*)d_in[2];
    const float* q_w      = (const float*)d_in[3];
    const float* k_w      = (const float*)d_in[4];
    const float* v_w      = (const float*)d_in[5];
    const float* o_w      = (const float*)d_in[6];
    const float* pre_attn = (const float*)d_in[7];
    const float* post_attn= (const float*)d_in[8];
    const float* pre_moe  = (const float*)d_in[9];
    const float* post_moe = (const float*)d_in[10];
    const float* gate_w   = (const float*)d_in[11];
    const float* w_in     = (const float*)d_in[12];
    const float* w_v      = (const float*)d_in[13];
    const float* w_out    = (const float*)d_in[14];
    float* out = (float*)d_out;

    float *q, *k, *v, *aproj, *x, *h2, *mid1, *mid2, *moe, *topw, *etw;
    int *topi, *tok, *cnt, *off;
    uint32_t *hnh, *hnl, *ath, *atl, *h2h, *h2l, *m1h, *m1l;
    uint32_t *qwh, *qwl, *kwh, *kwl, *vwh, *vwl, *owh, *owl;
    uint32_t *wih, *wil, *wvh, *wvl, *woh, *wol;
    SYMADDR(g_q, q); SYMADDR(g_k, k); SYMADDR(g_v, v);
    SYMADDR(g_aproj, aproj); SYMADDR(g_x, x); SYMADDR(g_h2, h2);
    SYMADDR(g_mid1, mid1); SYMADDR(g_mid2, mid2); SYMADDR(g_moe, moe);
    SYMADDR(g_topi, topi); SYMADDR(g_topw, topw);
    SYMADDR(g_tok, tok); SYMADDR(g_etw, etw); SYMADDR(g_cnt, cnt); SYMADDR(g_off, off);
    SYMADDR(g_hnh, hnh); SYMADDR(g_hnl, hnl); SYMADDR(g_ath, ath); SYMADDR(g_atl, atl);
    SYMADDR(g_h2h, h2h); SYMADDR(g_h2l, h2l); SYMADDR(g_m1h, m1h); SYMADDR(g_m1l, m1l);
    SYMADDR(g_qwh, qwh); SYMADDR(g_qwl, qwl); SYMADDR(g_kwh, kwh); SYMADDR(g_kwl, kwl);
    SYMADDR(g_vwh, vwh); SYMADDR(g_vwl, vwl); SYMADDR(g_owh, owh); SYMADDR(g_owl, owl);
    SYMADDR(g_wih, wih); SYMADDR(g_wil, wil); SYMADDR(g_wvh, wvh); SYMADDR(g_wvl, wvl);
    SYMADDR(g_woh, woh); SYMADDR(g_wol, wol);

    // opt-in dyn smem (idempotent, non-stream)
    cudaFuncSetAttribute((const void*)flash_attn_kernel,
                         cudaFuncAttributeMaxDynamicSharedMemorySize, FA_SMEM_BYTES);
    cudaFuncSetAttribute((const void*)qkv_kernel,
                         cudaFuncAttributeMaxDynamicSharedMemorySize, GEMM_SMEM);
    cudaFuncSetAttribute((const void*)oproj_kernel,
                         cudaFuncAttributeMaxDynamicSharedMemorySize, GEMM_SMEM);
    cudaFuncSetAttribute((const void*)moe_stage1_kernel,
                         cudaFuncAttributeMaxDynamicSharedMemorySize, GEMM_SMEM);
    cudaFuncSetAttribute((const void*)moe_stage2_kernel,
                         cudaFuncAttributeMaxDynamicSharedMemorySize, GEMM_SMEM);

    // 0) weight splits
    wconv_kernel<<<wblocks(512, 1024), 256>>>(q_w, qwh, qwl, 512, 1024);
    wconv_kernel<<<wblocks(512, 256), 256>>>(k_w, kwh, kwl, 512, 256);
    wconv_kernel<<<wblocks(512, 256), 256>>>(v_w, vwh, vwl, 512, 256);
    wconv_kernel<<<wblocks(512, 1024), 256>>>(o_w, owh, owl, 512, 1024);
    wconv_kernel<<<wblocks(8L * 512, 4096), 256>>>(w_in, wih, wil, 8L * 512, 4096);
    wconv_kernel<<<wblocks(8L * 512, 4096), 256>>>(w_v, wvh, wvl, 8L * 512, 4096);
    wconv_kernel<<<wblocks(8L * 2048, 1024), 256>>>(w_out, woh, wol, 8L * 2048, 1024);

    // 1) pre-attn rmsnorm -> packed split
    rmsnorm_kernel<<<CT, 256>>>(hidden, pre_attn, nullptr, nullptr, hnh, hnl);

    // 2) fused QKV projections
    qkv_kernel<<<dim3(12, CT / 128), 256, GEMM_SMEM>>>(
        hnh, hnl, qwh, qwl, kwh, kwl, vwh, vwl, q, k, v);

    // 3) RoPE
    rope_kernel<<<(CT * 20 * 32) / 256, 256>>>(q, k, posids);

    // 4) fused flash attention -> packed split attn
    flash_attn_kernel<<<dim3(CS / 64, CB * CNH), 256, FA_SMEM_BYTES>>>(
        q, k, v, amask, ath, atl);

    // 5) output projection + post-attn rmsnorm + residual
    oproj_kernel<<<dim3(CH / 128, CT / 128), 256, GEMM_SMEM>>>(ath, atl, owh, owl, aproj);
    rmsnorm_kernel<<<CT, 256>>>(aproj, post_attn, hidden, x, nullptr, nullptr);

    // 6) pre-moe rmsnorm -> fp32 (gate) + packed split (stage1)
    rmsnorm_kernel<<<CT, 256>>>(x, pre_moe, nullptr, h2, h2h, h2l);

    // 7) gating + routing
    gate_kernel<<<CT, 128>>>(h2, gate_w, topi, topw);
    route_kernel<<<1, 256>>>(topi, topw, tok, etw, cnt, off);

    // 8) sparse MoE
    zero_kernel<<<(CT * CH) / 256, 256>>>(moe);
    moe_stage1_kernel<<<dim3(CI / 128, CT / 128, CE * 2), 256, GEMM_SMEM>>>(
        h2h, h2l, wih, wil, wvh, wvl, mid1, mid2, tok, cnt, off);
    glu_kernel<<<dim3(CI / 512, CSLOTS), 256>>>(mid1, mid2, m1h, m1l, off);
    moe_stage2_kernel<<<dim3(CH / 128, CT / 128, CE), 256, GEMM_SMEM>>>(
        m1h, m1l, woh, wol, moe, tok, etw, cnt, off);

    // 9) post-moe rmsnorm + residual -> output
    rmsnorm_kernel<<<CT, 256>>>(moe, post_moe, x, out, nullptr, nullptr);
}

// round 17
// speedup vs baseline: 1.0116x; 1.0116x over previous
#include <cuda_runtime.h>
#include <math.h>
#include <stdint.h>

// ---------------- problem constants ----------------
constexpr int CB   = 2;
constexpr int CS   = 1024;
constexpr int CH   = 1024;
constexpr int CNH  = 16;
constexpr int CNKV = 4;
constexpr int CDH  = 64;
constexpr int CI   = 4096;
constexpr int CE   = 8;
constexpr int CT   = CB * CS;          // 2048 tokens
constexpr int CSLOTS = 2 * CT;
constexpr float CEPS = 1e-5f;

// ---------------- device scratch ----------------
__device__ float g_q[CT * CNH * CDH];
__device__ float g_k[CT * CNKV * CDH];
__device__ float g_v[CT * CNKV * CDH];
__device__ float g_aproj[CT * CH];
__device__ float g_x[CT * CH];
__device__ float g_h2[CT * CH];
__device__ float g_mid1[(long)CSLOTS * CI];
__device__ float g_mid2[(long)CSLOTS * CI];
__device__ float g_moe[CT * CH];
__device__ int   g_topi[CT * 2];
__device__ float g_topw[CT * 2];
__device__ int   g_tok[CE * CT];
__device__ float g_etw[CE * CT];
__device__ int   g_cnt[CE];
__device__ int   g_off[CE + 1];
// packed bf16x2 (even_k lo16, odd_k hi16) hi/lo split activations
__device__ uint32_t g_hnh[CT * 512], g_hnl[CT * 512];
__device__ uint32_t g_ath[CT * 512], g_atl[CT * 512];
__device__ uint32_t g_h2h[CT * 512], g_h2l[CT * 512];
__device__ uint32_t g_m1h[(long)CSLOTS * 2048], g_m1l[(long)CSLOTS * 2048];
// packed split weights
__device__ uint32_t g_qwh[512 * 1024], g_qwl[512 * 1024];
__device__ uint32_t g_kwh[512 * 256],  g_kwl[512 * 256];
__device__ uint32_t g_vwh[512 * 256],  g_vwl[512 * 256];
__device__ uint32_t g_owh[512 * 1024], g_owl[512 * 1024];
__device__ uint32_t g_wih[(long)8 * 512 * 4096],  g_wil[(long)8 * 512 * 4096];
__device__ uint32_t g_wvh[(long)8 * 512 * 4096],  g_wvl[(long)8 * 512 * 4096];
__device__ uint32_t g_woh[(long)8 * 2048 * 1024], g_wol[(long)8 * 2048 * 1024];

// ---------------- bf16 split helpers (verified) ----------------
__device__ __forceinline__ uint32_t bf16_rne_bits(float x) {
    uint32_t u = __float_as_uint(x);
    uint32_t r = u + 0x7FFFu + ((u >> 16) & 1u);
    return r & 0xFFFF0000u;
}
__device__ __forceinline__ void split_pack(float x0, float x1, uint32_t& hi, uint32_t& lo) {
    uint32_t h0b = bf16_rne_bits(x0);
    uint32_t h1b = bf16_rne_bits(x1);
    float l0 = x0 - __uint_as_float(h0b);
    float l1 = x1 - __uint_as_float(h1b);
    uint32_t l0b = bf16_rne_bits(l0);
    uint32_t l1b = bf16_rne_bits(l1);
    hi = (h0b >> 16) | (h1b & 0xFFFF0000u);
    lo = (l0b >> 16) | (l1b & 0xFFFF0000u);
}

__device__ __forceinline__ void mma_bf16(float* c, const uint32_t* a, const uint32_t* b) {
    asm volatile(
        "mma.sync.aligned.m16n8k16.row.col.f32.bf16.bf16.f32 "
        "{%0,%1,%2,%3}, {%4,%5,%6,%7}, {%8,%9}, {%0,%1,%2,%3};"
        : "+f"(c[0]), "+f"(c[1]), "+f"(c[2]), "+f"(c[3])
        : "r"(a[0]), "r"(a[1]), "r"(a[2]), "r"(a[3]), "r"(b[0]), "r"(b[1]));
}

// ---------------- cp.async helpers ----------------
__device__ __forceinline__ uint32_t smem_u32(const void* p) {
    uint32_t a;
    asm("{ .reg .u64 t; cvta.to.shared.u64 t, %1; cvt.u32.u64 %0, t; }" : "=r"(a) : "l"(p));
    return a;
}
__device__ __forceinline__ void cp16(uint32_t dst, const void* src, int sz) {
    asm volatile("cp.async.cg.shared.global [%0], [%1], 16, %2;"
                 :: "r"(dst), "l"(src), "r"(sz) : "memory");
}
#define CP_COMMIT() asm volatile("cp.async.commit_group;" ::: "memory")
#define CP_WAIT0()  asm volatile("cp.async.wait_group 0;" ::: "memory")

// ================= bf16x3 mma GEMM core, BK=32, dynamic smem =================
constexpr int GA_STRIDE = 20;
constexpr int GA_BUF = 128 * GA_STRIDE;
constexpr int GB_STRIDE = 136;
constexpr int GB_BUF = 16 * GB_STRIDE;
constexpr int GEMM_SMEM = (2 * GA_BUF * 2 + 2 * GB_BUF * 2) * 4;   // 75776 B

template <bool GATHER, bool SCATTER>
__device__ __forceinline__ void gemm_core(
    const uint32_t* __restrict__ Ah, const uint32_t* __restrict__ Al, int lda2,
    const uint32_t* __restrict__ Bh, const uint32_t* __restrict__ Bl, int ldb,
    float* __restrict__ C, int ldc,
    int M, int K,
    int row_base, int col_base,
    const int* __restrict__ row_idx, const float* __restrict__ row_w)
{
    extern __shared__ uint32_t dsm[];
    uint32_t* sAh = dsm;
    uint32_t* sAl = dsm + 2 * GA_BUF;
    uint32_t* sBh = dsm + 4 * GA_BUF;
    uint32_t* sBl = dsm + 4 * GA_BUF + 2 * GB_BUF;

    int tid  = threadIdx.x;
    int lane = tid & 31;
    int warp = tid >> 5;
    int g  = lane >> 2;
    int t4 = lane & 3;
    int m_warp = (warp & 3) * 32;
    int n_warp = (warp >> 2) * 64;

    int m_l = tid >> 1;
    int kq  = (tid & 1) * 8;
    int ar  = row_base + m_l;
    bool aval = ar < M;
    const uint32_t* ah_src = Ah;
    const uint32_t* al_src = Al;
    if (aval) {
        int r = GATHER ? row_idx[ar] : ar;
        long ro = (long)r * lda2 + kq;
        ah_src = Ah + ro; al_src = Al + ro;
    }
    int azf = aval ? 16 : 0;
    uint32_t adst0 = smem_u32(&sAh[m_l * GA_STRIDE + kq]);
    uint32_t adst1 = smem_u32(&sAl[m_l * GA_STRIDE + kq]);
    int kr = tid >> 4;
    int nq = (tid & 15) * 8;
    const uint32_t* bh_src = Bh + (long)kr * ldb + col_base + nq;
    const uint32_t* bl_src = Bl + (long)kr * ldb + col_base + nq;
    uint32_t bdst0 = smem_u32(&sBh[kr * GB_STRIDE + nq]);
    uint32_t bdst1 = smem_u32(&sBl[kr * GB_STRIDE + nq]);

    float acc[2][8][4];
#pragma unroll
    for (int i = 0; i < 2; i++)
#pragma unroll
        for (int j = 0; j < 8; j++)
#pragma unroll
            for (int l = 0; l < 4; l++) acc[i][j][l] = 0.f;

    {
        cp16(adst0,      ah_src,     azf);
        cp16(adst0 + 16, ah_src + 4, azf);
        cp16(adst1,      al_src,     azf);
        cp16(adst1 + 16, al_src + 4, azf);
        cp16(bdst0,      bh_src,     16);
        cp16(bdst0 + 16, bh_src + 4, 16);
        cp16(bdst1,      bl_src,     16);
        cp16(bdst1 + 16, bl_src + 4, 16);
        CP_COMMIT();
    }

    int KT = K >> 5;
    for (int kt = 0; kt < KT; kt++) {
        CP_WAIT0();
        __syncthreads();
        if (kt + 1 < KT) {
            int nb = (kt + 1) & 1;
            long ao = (long)(kt + 1) * 16;
            long bo = (long)(kt + 1) * 16 * ldb;
            uint32_t aoff = (uint32_t)(nb * GA_BUF * 4);
            uint32_t boff = (uint32_t)(nb * GB_BUF * 4);
            cp16(adst0 + aoff,      ah_src + ao,     azf);
            cp16(adst0 + aoff + 16, ah_src + ao + 4, azf);
            cp16(adst1 + aoff,      al_src + ao,     azf);
            cp16(adst1 + aoff + 16, al_src + ao + 4, azf);
            cp16(bdst0 + boff,      bh_src + bo,     16);
            cp16(bdst0 + boff + 16, bh_src + bo + 4, 16);
            cp16(bdst1 + boff,      bl_src + bo,     16);
            cp16(bdst1 + boff + 16, bl_src + bo + 4, 16);
            CP_COMMIT();
        }

        int buf = kt & 1;
        const uint32_t* cAh = sAh + buf * GA_BUF;
        const uint32_t* cAl = sAl + buf * GA_BUF;
        const uint32_t* cBh = sBh + buf * GB_BUF;
        const uint32_t* cBl = sBl + buf * GB_BUF;
#pragma unroll
        for (int ks = 0; ks < 2; ks++) {
            int kpb = ks * 8;
            uint32_t ah[2][4], al[2][4];
#pragma unroll
            for (int mf = 0; mf < 2; mf++) {
                int mb = m_warp + mf * 16 + g;
                ah[mf][0] = cAh[mb * GA_STRIDE + kpb + t4];
                al[mf][0] = cAl[mb * GA_STRIDE + kpb + t4];
                ah[mf][1] = cAh[(mb + 8) * GA_STRIDE + kpb + t4];
                al[mf][1] = cAl[(mb + 8) * GA_STRIDE + kpb + t4];
                ah[mf][2] = cAh[mb * GA_STRIDE + kpb + t4 + 4];
                al[mf][2] = cAl[mb * GA_STRIDE + kpb + t4 + 4];
                ah[mf][3] = cAh[(mb + 8) * GA_STRIDE + kpb + t4 + 4];
                al[mf][3] = cAl[(mb + 8) * GA_STRIDE + kpb + t4 + 4];
            }
            uint32_t bh[8][2], bl[8][2];
#pragma unroll
            for (int nf = 0; nf < 8; nf++) {
                int nb2 = n_warp + nf * 8 + g;
                bh[nf][0] = cBh[(kpb + t4) * GB_STRIDE + nb2];
                bl[nf][0] = cBl[(kpb + t4) * GB_STRIDE + nb2];
                bh[nf][1] = cBh[(kpb + t4 + 4) * GB_STRIDE + nb2];
                bl[nf][1] = cBl[(kpb + t4 + 4) * GB_STRIDE + nb2];
            }
#pragma unroll
            for (int mf = 0; mf < 2; mf++)
#pragma unroll
                for (int nf = 0; nf < 8; nf++) {
                    mma_bf16(acc[mf][nf], ah[mf], bh[nf]);
                    mma_bf16(acc[mf][nf], al[mf], bh[nf]);
                    mma_bf16(acc[mf][nf], ah[mf], bl[nf]);
                }
        }
    }

#pragma unroll
    for (int mf = 0; mf < 2; mf++) {
        int r0 = row_base + m_warp + mf * 16 + g;
        int r1 = r0 + 8;
        bool v0 = r0 < M, v1 = r1 < M;
        if (!SCATTER) {
#pragma unroll
            for (int nf = 0; nf < 8; nf++) {
                int c = col_base + n_warp + nf * 8 + t4 * 2;
                if (v0) *(float2*)&C[(long)r0 * ldc + c] = make_float2(acc[mf][nf][0], acc[mf][nf][1]);
                if (v1) *(float2*)&C[(long)r1 * ldc + c] = make_float2(acc[mf][nf][2], acc[mf][nf][3]);
            }
        } else {
            int tk0 = 0, tk1 = 0; float w0 = 0.f, w1 = 0.f;
            if (v0) { tk0 = row_idx[r0]; w0 = row_w[r0]; }
            if (v1) { tk1 = row_idx[r1]; w1 = row_w[r1]; }
#pragma unroll
            for (int nf = 0; nf < 8; nf++) {
                int c = col_base + n_warp + nf * 8 + t4 * 2;
                if (v0) {
                    atomicAdd(&C[(long)tk0 * ldc + c],     w0 * acc[mf][nf][0]);
                    atomicAdd(&C[(long)tk0 * ldc + c + 1], w0 * acc[mf][nf][1]);
                }
                if (v1) {
                    atomicAdd(&C[(long)tk1 * ldc + c],     w1 * acc[mf][nf][2]);
                    atomicAdd(&C[(long)tk1 * ldc + c + 1], w1 * acc[mf][nf][3]);
                }
            }
        }
    }
}

// ---------------- weight convert: grid-stride, 8 floats/thread/iter ----------------
__global__ __launch_bounds__(256) void wconv_kernel(
    const float* __restrict__ in, uint32_t* __restrict__ oh, uint32_t* __restrict__ ol,
    long kp_total, int N)
{
    long work = kp_total * (long)(N >> 3);
    long stride = (long)gridDim.x * 256;
    for (long idx = (long)blockIdx.x * 256 + threadIdx.x; idx < work; idx += stride) {
        long kp = idx / (N >> 3);
        int  nq = (int)(idx % (N >> 3));
        const float* p0 = in + (2 * kp) * (long)N + 8 * nq;
        float4 a0 = *(const float4*)p0;
        float4 a1 = *(const float4*)(p0 + 4);
        float4 b0 = *(const float4*)(p0 + N);
        float4 b1 = *(const float4*)(p0 + N + 4);
        uint4 h0, l0, h1, l1;
        split_pack(a0.x, b0.x, h0.x, l0.x);
        split_pack(a0.y, b0.y, h0.y, l0.y);
        split_pack(a0.z, b0.z, h0.z, l0.z);
        split_pack(a0.w, b0.w, h0.w, l0.w);
        split_pack(a1.x, b1.x, h1.x, l1.x);
        split_pack(a1.y, b1.y, h1.y, l1.y);
        split_pack(a1.z, b1.z, h1.z, l1.z);
        split_pack(a1.w, b1.w, h1.w, l1.w);
        long o = kp * (long)N + 8 * nq;
        *(uint4*)&oh[o]     = h0;
        *(uint4*)&oh[o + 4] = h1;
        *(uint4*)&ol[o]     = l0;
        *(uint4*)&ol[o + 4] = l1;
    }
}

// ---------------- rmsnorm: optional residual / fp32 out / packed out ----------------
__global__ __launch_bounds__(256) void rmsnorm_kernel(
    const float* __restrict__ in, const float* __restrict__ sc,
    const float* __restrict__ resid, float* __restrict__ out,
    uint32_t* __restrict__ outh, uint32_t* __restrict__ outl)
{
    long row = blockIdx.x;
    int tid = threadIdx.x;
    float4 v = *(const float4*)(in + row * CH + tid * 4);
    float ss = v.x * v.x + v.y * v.y + v.z * v.z + v.w * v.w;
    __shared__ float red[256];
    red[tid] = ss;
    __syncthreads();
    for (int s = 128; s > 0; s >>= 1) {
        if (tid < s) red[tid] += red[tid + s];
        __syncthreads();
    }
    float r = rsqrtf(red[0] * (1.0f / CH) + CEPS);
    float4 s4 = *(const float4*)(sc + tid * 4);
    float o0 = v.x * r * s4.x, o1 = v.y * r * s4.y, o2 = v.z * r * s4.z, o3 = v.w * r * s4.w;
    if (resid) {
        float4 rr = *(const float4*)(resid + row * CH + tid * 4);
        o0 += rr.x; o1 += rr.y; o2 += rr.z; o3 += rr.w;
    }
    if (out) *(float4*)(out + row * CH + tid * 4) = make_float4(o0, o1, o2, o3);
    if (outh) {
        uint32_t h0, l0, h1, l1;
        split_pack(o0, o1, h0, l0);
        split_pack(o2, o3, h1, l1);
        *(uint2*)&outh[row * 512 + tid * 2] = make_uint2(h0, h1);
        *(uint2*)&outl[row * 512 + tid * 2] = make_uint2(l0, l1);
    }
}

// ---------------- GEMM wrappers ----------------
__global__ __launch_bounds__(256) void qkv_kernel(
    const uint32_t* __restrict__ hnh, const uint32_t* __restrict__ hnl,
    const uint32_t* __restrict__ qwh, const uint32_t* __restrict__ qwl,
    const uint32_t* __restrict__ kwh, const uint32_t* __restrict__ kwl,
    const uint32_t* __restrict__ vwh, const uint32_t* __restrict__ vwl,
    float* __restrict__ q, float* __restrict__ k, float* __restrict__ v)
{
    int x = blockIdx.x;
    const uint32_t *Bh, *Bl; float* C; int ld; int col;
    if (x < 8)       { Bh = qwh; Bl = qwl; C = q; ld = 1024; col = x * 128; }
    else if (x < 10) { Bh = kwh; Bl = kwl; C = k; ld = 256;  col = (x - 8) * 128; }
    else             { Bh = vwh; Bl = vwl; C = v; ld = 256;  col = (x - 10) * 128; }
    gemm_core<false, false>(hnh, hnl, 512, Bh, Bl, ld, C, ld, CT, CH,
                            blockIdx.y * 128, col, nullptr, nullptr);
}

__global__ __launch_bounds__(256) void oproj_kernel(
    const uint32_t* __restrict__ ath, const uint32_t* __restrict__ atl,
    const uint32_t* __restrict__ owh, const uint32_t* __restrict__ owl,
    float* __restrict__ aproj)
{
    gemm_core<false, false>(ath, atl, 512, owh, owl, CH, aproj, CH, CT, CH,
                            blockIdx.y * 128, blockIdx.x * 128, nullptr, nullptr);
}

__global__ __launch_bounds__(256) void moe_stage1_kernel(
    const uint32_t* __restrict__ h2h, const uint32_t* __restrict__ h2l,
    const uint32_t* __restrict__ wih, const uint32_t* __restrict__ wil,
    const uint32_t* __restrict__ wvh, const uint32_t* __restrict__ wvl,
    float* __restrict__ mid1, float* __restrict__ mid2,
    const int* __restrict__ tok, const int* __restrict__ cnt, const int* __restrict__ off)
{
    int z = blockIdx.z;
    int e = z >> 1;
    int which = z & 1;
    int M = cnt[e];
    int row_base = blockIdx.y * 128;
    if (row_base >= M) return;
    const uint32_t* Bh = (which ? wvh : wih) + (long)e * 512 * CI;
    const uint32_t* Bl = (which ? wvl : wil) + (long)e * 512 * CI;
    float* C = (which ? mid2 : mid1) + (long)off[e] * CI;
    gemm_core<true, false>(h2h, h2l, 512, Bh, Bl, CI, C, CI, M, CH,
                           row_base, blockIdx.x * 128, tok + e * CT, nullptr);
}

__global__ __launch_bounds__(256) void moe_stage2_kernel(
    const uint32_t* __restrict__ m1h, const uint32_t* __restrict__ m1l,
    const uint32_t* __restrict__ woh, const uint32_t* __restrict__ wol,
    float* __restrict__ moe,
    const int* __restrict__ tok, const float* __restrict__ etw,
    const int* __restrict__ cnt, const int* __restrict__ off)
{
    int e = blockIdx.z;
    int M = cnt[e];
    int row_base = blockIdx.y * 128;
    if (row_base >= M) return;
    const uint32_t* Ah = m1h + (long)off[e] * 2048;
    const uint32_t* Al = m1l + (long)off[e] * 2048;
    const uint32_t* Bh = woh + (long)e * 2048 * CH;
    const uint32_t* Bl = wol + (long)e * 2048 * CH;
    gemm_core<false, true>(Ah, Al, 2048, Bh, Bl, CH, moe, CH, M, CI,
                           row_base, blockIdx.x * 128, tok + e * CT, etw + e * CT);
}

// ---------------- RoPE ----------------
__global__ __launch_bounds__(256) void rope_kernel(
    float* __restrict__ q, float* __restrict__ k, const int* __restrict__ pos)
{
    long idx = (long)blockIdx.x * 256 + threadIdx.x;
    if (idx >= (long)CT * 20 * 32) return;
    int d = idx & 31;
    int hh = (int)((idx >> 5) % 20);
    int t = (int)(idx / (32 * 20));
    float p = (float)pos[t];
    float inv = powf(10000.0f, -((float)d) / 32.0f);
    float ang = p * inv;
    float c = cosf(ang), s = sinf(ang);
    float* ptr;
    if (hh < CNH) ptr = q + (long)t * (CNH * CDH) + hh * CDH;
    else          ptr = k + (long)t * (CNKV * CDH) + (hh - CNH) * CDH;
    float x1 = ptr[d], x2 = ptr[d + 32];
    ptr[d]      = x1 * c - x2 * s;
    ptr[d + 32] = x2 * c + x1 * s;
}

// ================= fused flash attention (verified; packed output) =================
constexpr int FA_STRIDE = 68;
constexpr int FA_REGION = 64 * FA_STRIDE;
constexpr int FA_SMEM_BYTES = 3 * FA_REGION * 4;

__global__ __launch_bounds__(256) void flash_attn_kernel(
    const float* __restrict__ q, const float* __restrict__ k, const float* __restrict__ v,
    const int* __restrict__ amask,
    uint32_t* __restrict__ attnh, uint32_t* __restrict__ attnl)
{
    extern __shared__ float sm[];
    float* Qs = sm;
    float* KP = sm + FA_REGION;
    float* Vs = sm + 2 * FA_REGION;

    int it = (int)gridDim.x - 1 - (int)blockIdx.x;
    int bh = blockIdx.y;
    int b = bh >> 4, h = bh & 15, kv = h >> 2;
    int tid = threadIdx.x;
    int ti = (tid >> 4) << 2;
    int tj = (tid & 15) << 2;

#pragma unroll
    for (int l = 0; l < 4; l++) {
        int e = tid + l * 256;
        int r = e >> 4;
        int c = (e & 15) << 2;
        float4 a = *(const float4*)(q + (long)(b * CS + it * 64 + r) * (CNH * CDH) + h * CDH + c);
        Qs[(c + 0) * FA_STRIDE + r] = a.x; Qs[(c + 1) * FA_STRIDE + r] = a.y;
        Qs[(c + 2) * FA_STRIDE + r] = a.z; Qs[(c + 3) * FA_STRIDE + r] = a.w;
    }

    float m_i[4], l_i[4], acc[4][4];
#pragma unroll
    for (int i = 0; i < 4; i++) {
        m_i[i] = -1e30f; l_i[i] = 0.f;
#pragma unroll
        for (int j = 0; j < 4; j++) acc[i][j] = 0.f;
    }

    for (int jt = 0; jt <= it; jt++) {
        __syncthreads();
#pragma unroll
        for (int l = 0; l < 4; l++) {
            int e = tid + l * 256;
            int r = e >> 4;
            int c = (e & 15) << 2;
            const float* kvbase = k + (long)(b * CS + jt * 64 + r) * (CNKV * CDH) + kv * CDH + c;
            float4 kk = *(const float4*)(kvbase);
            KP[(c + 0) * FA_STRIDE + r] = kk.x; KP[(c + 1) * FA_STRIDE + r] = kk.y;
            KP[(c + 2) * FA_STRIDE + r] = kk.z; KP[(c + 3) * FA_STRIDE + r] = kk.w;
            float4 vv = *(const float4*)(v + (long)(b * CS + jt * 64 + r) * (CNKV * CDH) + kv * CDH + c);
            *(float4*)&Vs[r * FA_STRIDE + c] = vv;
        }
        __syncthreads();

        float s[4][4] = {};
#pragma unroll 8
        for (int d = 0; d < 64; d++) {
            float4 a = *(const float4*)&Qs[d * FA_STRIDE + ti];
            float4 bb = *(const float4*)&KP[d * FA_STRIDE + tj];
            float af[4] = {a.x, a.y, a.z, a.w};
            float bf[4] = {bb.x, bb.y, bb.z, bb.w};
#pragma unroll
            for (int i = 0; i < 4; i++)
#pragma unroll
                for (int j = 0; j < 4; j++) s[i][j] += af[i] * bf[j];
        }

        int ig0 = it * 64 + ti;
        int jg0 = jt * 64 + tj;
        int msk[4];
#pragma unroll
        for (int j = 0; j < 4; j++) msk[j] = amask[b * CS + jg0 + j];
#pragma unroll
        for (int i = 0; i < 4; i++)
#pragma unroll
            for (int j = 0; j < 4; j++) {
                bool valid = (jg0 + j <= ig0 + i) && (msk[j] > 0);
                s[i][j] = valid ? s[i][j] * 0.125f : -1e9f;
            }

        float p[4][4];
#pragma unroll
        for (int i = 0; i < 4; i++) {
            float mx = fmaxf(fmaxf(s[i][0], s[i][1]), fmaxf(s[i][2], s[i][3]));
#pragma unroll
            for (int d = 1; d < 16; d <<= 1)
                mx = fmaxf(mx, __shfl_xor_sync(0xFFFFFFFFu, mx, d));
            float nm = fmaxf(m_i[i], mx);
            float alpha = expf(m_i[i] - nm);
            float rs = 0.f;
#pragma unroll
            for (int j = 0; j < 4; j++) { p[i][j] = expf(s[i][j] - nm); rs += p[i][j]; }
#pragma unroll
            for (int d = 1; d < 16; d <<= 1)
                rs += __shfl_xor_sync(0xFFFFFFFFu, rs, d);
            l_i[i] = l_i[i] * alpha + rs;
            m_i[i] = nm;
#pragma unroll
            for (int j = 0; j < 4; j++) acc[i][j] *= alpha;
        }

        __syncthreads();
#pragma unroll
        for (int i = 0; i < 4; i++)
            *(float4*)&KP[(ti + i) * FA_STRIDE + tj] =
                make_float4(p[i][0], p[i][1], p[i][2], p[i][3]);
        __syncthreads();

#pragma unroll 4
        for (int jc = 0; jc < 64; jc += 4) {
            float4 pr[4], vr[4];
#pragma unroll
            for (int i = 0; i < 4; i++) pr[i] = *(const float4*)&KP[(ti + i) * FA_STRIDE + jc];
#pragma unroll
            for (int j = 0; j < 4; j++) vr[j] = *(const float4*)&Vs[(jc + j) * FA_STRIDE + tj];
#pragma unroll
            for (int i = 0; i < 4; i++) {
                float pf[4] = {pr[i].x, pr[i].y, pr[i].z, pr[i].w};
#pragma unroll
                for (int j = 0; j < 4; j++) {
                    acc[i][0] += pf[j] * vr[j].x;
                    acc[i][1] += pf[j] * vr[j].y;
                    acc[i][2] += pf[j] * vr[j].z;
                    acc[i][3] += pf[j] * vr[j].w;
                }
            }
        }
    }

#pragma unroll
    for (int i = 0; i < 4; i++) {
        float inv = 1.0f / l_i[i];
        float o0 = acc[i][0] * inv, o1 = acc[i][1] * inv;
        float o2 = acc[i][2] * inv, o3 = acc[i][3] * inv;
        uint32_t h0, l0, h1, l1;
        split_pack(o0, o1, h0, l0);
        split_pack(o2, o3, h1, l1);
        long rb = (long)(b * CS + it * 64 + ti + i) * 512 + ((h * CDH + tj) >> 1);
        *(uint2*)&attnh[rb] = make_uint2(h0, h1);
        *(uint2*)&attnl[rb] = make_uint2(l0, l1);
    }
}

// ---------------- MoE gating ----------------
__global__ __launch_bounds__(128) void gate_kernel(
    const float* __restrict__ h2, const float* __restrict__ gw,
    int* __restrict__ topi, float* __restrict__ topw)
{
    int t = blockIdx.x;
    int tid = threadIdx.x;
    float p[8] = {};
    for (int hh = tid; hh < CH; hh += 128) {
        float x = h2[(long)t * CH + hh];
        const float* g = gw + hh * CE;
#pragma unroll
        for (int e = 0; e < 8; e++) p[e] += x * g[e];
    }
    __shared__ float red[128 * 8];
#pragma unroll
    for (int e = 0; e < 8; e++) red[tid * 8 + e] = p[e];
    __syncthreads();
    for (int s = 64; s > 0; s >>= 1) {
        if (tid < s)
#pragma unroll
            for (int e = 0; e < 8; e++) red[tid * 8 + e] += red[(tid + s) * 8 + e];
        __syncthreads();
    }
    if (tid == 0) {
        float lg[8], pr[8];
        float m = -1e30f;
#pragma unroll
        for (int e = 0; e < 8; e++) { lg[e] = red[e]; m = fmaxf(m, lg[e]); }
        float sum = 0.f;
#pragma unroll
        for (int e = 0; e < 8; e++) { pr[e] = expf(lg[e] - m); sum += pr[e]; }
        float inv = 1.0f / sum;
#pragma unroll
        for (int e = 0; e < 8; e++) pr[e] *= inv;
        int i0 = 0;
#pragma unroll
        for (int e = 1; e < 8; e++) if (pr[e] > pr[i0]) i0 = e;
        int i1 = -1;
#pragma unroll
        for (int e = 0; e < 8; e++) {
            if (e == i0) continue;
            if (i1 < 0 || pr[e] > pr[i1]) i1 = e;
        }
        topi[t * 2] = i0; topi[t * 2 + 1] = i1;
        topw[t * 2] = pr[i0]; topw[t * 2 + 1] = pr[i1];
    }
}

// ---------------- routing ----------------
__global__ __launch_bounds__(256) void route_kernel(
    const int* __restrict__ topi, const float* __restrict__ topw,
    int* __restrict__ tok, float* __restrict__ etw,
    int* __restrict__ cnt, int* __restrict__ off)
{
    int e = threadIdx.x >> 5;
    int lane = threadIdx.x & 31;
    int count = 0;
    for (int base = 0; base < CT; base += 32) {
        int t = base + lane;
        int i0 = topi[t * 2], i1 = topi[t * 2 + 1];
        bool sel = (i0 == e) || (i1 == e);
        float w = (i0 == e) ? topw[t * 2] : topw[t * 2 + 1];
        unsigned m = __ballot_sync(0xFFFFFFFFu, sel);
        int pos = count + __popc(m & ((1u << lane) - 1u));
        if (sel) {
            tok[e * CT + pos] = t;
            etw[e * CT + pos] = w;
        }
        count += __popc(m);
    }
    if (lane == 0) cnt[e] = count;
    __syncthreads();
    if (threadIdx.x == 0) {
        int s = 0;
        for (int i = 0; i < CE; i++) { off[i] = s; s += cnt[i]; }
        off[CE] = s;
    }
}

// ---------------- GEGLU -> packed split ----------------
__global__ __launch_bounds__(256) void glu_kernel(
    const float* __restrict__ m1, const float* __restrict__ m2,
    uint32_t* __restrict__ oh, uint32_t* __restrict__ ol,
    const int* __restrict__ off)
{
    int row = blockIdx.y;
    if (row >= off[CE]) return;
    int p = blockIdx.x * 256 + threadIdx.x;
    long base = (long)row * CI + 2 * p;
    float2 a = *(const float2*)&m1[base];
    float2 b = *(const float2*)&m2[base];
    float g0 = 0.5f * a.x * (1.0f + tanhf(0.7978845608028654f * (a.x + 0.044715f * a.x * a.x * a.x))) * b.x;
    float g1 = 0.5f * a.y * (1.0f + tanhf(0.7978845608028654f * (a.y + 0.044715f * a.y * a.y * a.y))) * b.y;
    uint32_t h, l;
    split_pack(g0, g1, h, l);
    oh[(long)row * 2048 + p] = h;
    ol[(long)row * 2048 + p] = l;
}

// ---------------- zero fill ----------------
__global__ __launch_bounds__(256) void zero_kernel(float* __restrict__ p)
{
    p[(long)blockIdx.x * 256 + threadIdx.x] = 0.f;
}

// ---------------- host orchestration ----------------
#define SYMADDR(var, ptr) do { void* _p = nullptr; cudaGetSymbolAddress(&_p, var); ptr = (decltype(ptr))_p; } while (0)

static inline int wblocks(long kp_total, int N) {
    long work = kp_total * (long)(N >> 3);
    long b = (work + 255) / 256;
    return (int)(b < 2048 ? b : 2048);
}

extern "C" void kernel_launch(void* const* d_in, const int* in_sizes, int n_in,
                              void* d_out, int out_size)
{
    const float* hidden   = (const float*)d_in[0];
    const int*   amask    = (const int*)d_in[1];
    const int*   posids   = (const int*)d_in[2];
    const float* q_w      = (const float*)d_in[3];
    const float* k_w      = (const float*)d_in[4];
    const float* v_w      = (const float*)d_in[5];
    const float* o_w      = (const float*)d_in[6];
    const float* pre_attn = (const float*)d_in[7];
    const float* post_attn= (const float*)d_in[8];
    const float* pre_moe  = (const float*)d_in[9];
    const float* post_moe = (const float*)d_in[10];
    const float* gate_w   = (const float*)d_in[11];
    const float* w_in     = (const float*)d_in[12];
    const float* w_v      = (const float*)d_in[13];
    const float* w_out    = (const float*)d_in[14];
    float* out = (float*)d_out;

    float *q, *k, *v, *aproj, *x, *h2, *mid1, *mid2, *moe, *topw, *etw;
    int *topi, *tok, *cnt, *off;
    uint32_t *hnh, *hnl, *ath, *atl, *h2h, *h2l, *m1h, *m1l;
    uint32_t *qwh, *qwl, *kwh, *kwl, *vwh, *vwl, *owh, *owl;
    uint32_t *wih, *wil, *wvh, *wvl, *woh, *wol;
    SYMADDR(g_q, q); SYMADDR(g_k, k); SYMADDR(g_v, v);
    SYMADDR(g_aproj, aproj); SYMADDR(g_x, x); SYMADDR(g_h2, h2);
    SYMADDR(g_mid1, mid1); SYMADDR(g_mid2, mid2); SYMADDR(g_moe, moe);
    SYMADDR(g_topi, topi); SYMADDR(g_topw, topw);
    SYMADDR(g_tok, tok); SYMADDR(g_etw, etw); SYMADDR(g_cnt, cnt); SYMADDR(g_off, off);
    SYMADDR(g_hnh, hnh); SYMADDR(g_hnl, hnl); SYMADDR(g_ath, ath); SYMADDR(g_atl, atl);
    SYMADDR(g_h2h, h2h); SYMADDR(g_h2l, h2l); SYMADDR(g_m1h, m1h); SYMADDR(g_m1l, m1l);
    SYMADDR(g_qwh, qwh); SYMADDR(g_qwl, qwl); SYMADDR(g_kwh, kwh); SYMADDR(g_kwl, kwl);
    SYMADDR(g_vwh, vwh); SYMADDR(g_vwl, vwl); SYMADDR(g_owh, owh); SYMADDR(g_owl, owl);
    SYMADDR(g_wih, wih); SYMADDR(g_wil, wil); SYMADDR(g_wvh, wvh); SYMADDR(g_wvl, wvl);
    SYMADDR(g_woh, woh); SYMADDR(g_wol, wol);

    // opt-in dyn smem (idempotent, non-stream)
    cudaFuncSetAttribute((const void*)flash_attn_kernel,
                         cudaFuncAttributeMaxDynamicSharedMemorySize, FA_SMEM_BYTES);
    cudaFuncSetAttribute((const void*)qkv_kernel,
                         cudaFuncAttributeMaxDynamicSharedMemorySize, GEMM_SMEM);
    cudaFuncSetAttribute((const void*)oproj_kernel,
                         cudaFuncAttributeMaxDynamicSharedMemorySize, GEMM_SMEM);
    cudaFuncSetAttribute((const void*)moe_stage1_kernel,
                         cudaFuncAttributeMaxDynamicSharedMemorySize, GEMM_SMEM);
    cudaFuncSetAttribute((const void*)moe_stage2_kernel,
                         cudaFuncAttributeMaxDynamicSharedMemorySize, GEMM_SMEM);

    // lazy-init side stream + events (created during the uncaptured correctness
    // call; reused on the capture call — host-side only, device work unchanged)
    static cudaStream_t s_side = nullptr;
    static cudaEvent_t ev_fork = nullptr, ev_side = nullptr;
    if (!s_side) {
        cudaStreamCreateWithFlags(&s_side, cudaStreamNonBlocking);
        cudaEventCreateWithFlags(&ev_fork, cudaEventDisableTiming);
        cudaEventCreateWithFlags(&ev_side, cudaEventDisableTiming);
    }

    // ---- fork: big MoE weight converts + moe zero on side stream ----
    cudaEventRecord(ev_fork, 0);
    cudaStreamWaitEvent(s_side, ev_fork, 0);
    wconv_kernel<<<wblocks(8L * 512, 4096), 256, 0, s_side>>>(w_in, wih, wil, 8L * 512, 4096);
    wconv_kernel<<<wblocks(8L * 512, 4096), 256, 0, s_side>>>(w_v, wvh, wvl, 8L * 512, 4096);
    wconv_kernel<<<wblocks(8L * 2048, 1024), 256, 0, s_side>>>(w_out, woh, wol, 8L * 2048, 1024);
    zero_kernel<<<(CT * CH) / 256, 256, 0, s_side>>>(moe);
    cudaEventRecord(ev_side, s_side);

    // ---- main chain (default stream) ----
    // attention-path weight splits
    wconv_kernel<<<wblocks(512, 1024), 256>>>(q_w, qwh, qwl, 512, 1024);
    wconv_kernel<<<wblocks(512, 256), 256>>>(k_w, kwh, kwl, 512, 256);
    wconv_kernel<<<wblocks(512, 256), 256>>>(v_w, vwh, vwl, 512, 256);
    wconv_kernel<<<wblocks(512, 1024), 256>>>(o_w, owh, owl, 512, 1024);

    // 1) pre-attn rmsnorm -> packed split
    rmsnorm_kernel<<<CT, 256>>>(hidden, pre_attn, nullptr, nullptr, hnh, hnl);

    // 2) fused QKV projections
    qkv_kernel<<<dim3(12, CT / 128), 256, GEMM_SMEM>>>(
        hnh, hnl, qwh, qwl, kwh, kwl, vwh, vwl, q, k, v);

    // 3) RoPE
    rope_kernel<<<(CT * 20 * 32) / 256, 256>>>(q, k, posids);

    // 4) fused flash attention -> packed split attn
    flash_attn_kernel<<<dim3(CS / 64, CB * CNH), 256, FA_SMEM_BYTES>>>(
        q, k, v, amask, ath, atl);

    // 5) output projection + post-attn rmsnorm + residual
    oproj_kernel<<<dim3(CH / 128, CT / 128), 256, GEMM_SMEM>>>(ath, atl, owh, owl, aproj);
    rmsnorm_kernel<<<CT, 256>>>(aproj, post_attn, hidden, x, nullptr, nullptr);

    // 6) pre-moe rmsnorm -> fp32 (gate) + packed split (stage1)
    rmsnorm_kernel<<<CT, 256>>>(x, pre_moe, nullptr, h2, h2h, h2l);

    // 7) gating + routing
    gate_kernel<<<CT, 128>>>(h2, gate_w, topi, topw);
    route_kernel<<<1, 256>>>(topi, topw, tok, etw, cnt, off);

    // ---- join: MoE weights + zeroed accumulator ready ----
    cudaStreamWaitEvent(0, ev_side, 0);

    // 8) sparse MoE
    moe_stage1_kernel<<<dim3(CI / 128, CT / 128, CE * 2), 256, GEMM_SMEM>>>(
        h2h, h2l, wih, wil, wvh, wvl, mid1, mid2, tok, cnt, off);
    glu_kernel<<<dim3(CI / 512, CSLOTS), 256>>>(mid1, mid2, m1h, m1l, off);
    moe_stage2_kernel<<<dim3(CH / 128, CT / 128, CE), 256, GEMM_SMEM>>>(
        m1h, m1l, woh, wol, moe, tok, etw, cnt, off);

    // 9) post-moe rmsnorm + residual -> output
    rmsnorm_kernel<<<CT, 256>>>(moe, post_moe, x, out, nullptr, nullptr);
}